// round 9
// baseline (speedup 1.0000x reference)
#include <cuda_runtime.h>
#include <cuda_bf16.h>
#include <cstdint>

// CausalTrajectoryPrediction: fused 3-GEMM MLP, mma.sync m16n8k16 bf16,
// register-chained, pre-repacked weights (R8). R9: 512-thread blocks
// (kBT=512, halves staging traffic), uint4 B-fragment loads (2 ksteps per
// LDS.128), hoisted X A-fragments, warp-parity branch staggering to
// desynchronize smem bursts across warps.

namespace {
constexpr int kB       = 16384;
constexpr int kBT      = 512;
constexpr int kThreads = 512;

// per-node repacked weights, uint2 units; uint4-pair layout:
// frag(s,n,t4) at uint2 idx ((s>>1)*NS + n)*8 + 2*t4 + (s&1)
//   BP1 [0,2048): [W1a;W2a] NS=128   (16 KB)
//   BP2 [2048,3072): W1b|W2b NS=32 per br ( 8 KB)
//   BP3 [3072,4096): W3a[:,0:64] NS=64    ( 8 KB)
constexpr int kBPN = 4096;

constexpr uint32_t OFF_X   = 0;          // bf16 [512][72] = 73728
constexpr uint32_t OFF_BP  = 73728;      // 32 KB
constexpr uint32_t OFF_XI  = 106496;     // float [512]
constexpr uint32_t OFF_W3X = 108544;     // float [64]
constexpr uint32_t OFF_B3A = 108800;     // float [64]
constexpr uint32_t OFF_W3B = 109056;     // float [64]
constexpr uint32_t OFF_B3B = 109312;     // float
constexpr uint32_t SMEM_BYTES = 109328;
} // namespace

__device__ uint2 g_bp[64 * kBPN];
__device__ float g_vec[64 * 256];

__device__ __forceinline__ uint32_t smem_u32(const void* p) {
    uint32_t a;
    asm("{ .reg .u64 t; cvta.to.shared.u64 t, %1; cvt.u32.u64 %0, t; }"
        : "=r"(a) : "l"(p));
    return a;
}
__device__ __forceinline__ uint32_t bf2(float a, float b) {
    __nv_bfloat162 h = __floats2bfloat162_rn(a, b);
    return *reinterpret_cast<uint32_t*>(&h);
}
__device__ __forceinline__ void ldmat4(uint32_t r[4], uint32_t saddr) {
    asm volatile("ldmatrix.sync.aligned.m8n8.x4.shared.b16 {%0,%1,%2,%3}, [%4];"
                 : "=r"(r[0]), "=r"(r[1]), "=r"(r[2]), "=r"(r[3]) : "r"(saddr));
}
__device__ __forceinline__ void mma16(float d[4], const uint32_t a[4],
                                      uint32_t b0, uint32_t b1) {
    asm volatile(
        "mma.sync.aligned.m16n8k16.row.col.f32.bf16.bf16.f32 "
        "{%0,%1,%2,%3}, {%4,%5,%6,%7}, {%8,%9}, {%0,%1,%2,%3};"
        : "+f"(d[0]), "+f"(d[1]), "+f"(d[2]), "+f"(d[3])
        : "r"(a[0]), "r"(a[1]), "r"(a[2]), "r"(a[3]), "r"(b0), "r"(b1));
}
__device__ __forceinline__ void pack2(uint32_t a[4], const float c0[4],
                                      const float c1[4]) {
    a[0] = bf2(fmaxf(c0[0], 0.f), fmaxf(c0[1], 0.f));
    a[1] = bf2(fmaxf(c0[2], 0.f), fmaxf(c0[3], 0.f));
    a[2] = bf2(fmaxf(c1[0], 0.f), fmaxf(c1[1], 0.f));
    a[3] = bf2(fmaxf(c1[2], 0.f), fmaxf(c1[3], 0.f));
}

// ---------------- repack kernel: one block per node ----------------
__global__ void __launch_bounds__(256)
ctp_repack_kernel(const float* __restrict__ W1a, const float* __restrict__ W1b,
                  const float* __restrict__ W2a, const float* __restrict__ W2b,
                  const float* __restrict__ W3a, const float* __restrict__ b3a,
                  const float* __restrict__ W3b, const float* __restrict__ b3b)
{
    const int node = blockIdx.x;
    const int tid  = threadIdx.x;
    uint2* bp1 = g_bp + (size_t)node * kBPN;
    uint2* bp2 = bp1 + 2048;
    uint2* bp3 = bp1 + 3072;

    {   // BP1: [W1a;W2a], NS=128
        const float* w1 = W1a + (size_t)node * 4096;
        const float* w2 = W2a + (size_t)node * 4096;
        for (int t = tid; t < 512; t += 256) {
            const int n = t >> 2, s = t & 3;
            const float* src = (n < 64) ? (w1 + n * 64 + s * 16)
                                        : (w2 + (n - 64) * 64 + s * 16);
            uint2* dst = bp1 + (size_t)((s >> 1) * 128 + n) * 8 + (s & 1);
            #pragma unroll
            for (int t4 = 0; t4 < 4; t4++)
                dst[2 * t4] = make_uint2(bf2(src[2 * t4],     src[2 * t4 + 1]),
                                         bf2(src[2 * t4 + 8], src[2 * t4 + 9]));
        }
    }
    {   // BP2: br0 = W1b, br1 = W2b; NS=32 within each br half
        for (int t = tid; t < 256; t += 256) {
            const int br = t >> 7, rem = t & 127, m = rem >> 2, s = rem & 3;
            const float* src = (br ? W2b : W1b) + (size_t)node * 2048 + m * 64 + s * 16;
            uint2* dst = bp2 + (size_t)br * 512
                             + (size_t)((s >> 1) * 32 + m) * 8 + (s & 1);
            #pragma unroll
            for (int t4 = 0; t4 < 4; t4++)
                dst[2 * t4] = make_uint2(bf2(src[2 * t4],     src[2 * t4 + 1]),
                                         bf2(src[2 * t4 + 8], src[2 * t4 + 9]));
        }
    }
    {   // BP3: W3a[:,0:64], NS=64
        const float* w3 = W3a + (size_t)node * 8192;
        for (int t = tid; t < 256; t += 256) {
            const int n = t >> 2, s = t & 3;
            const float* src = w3 + n * 128 + s * 16;
            uint2* dst = bp3 + (size_t)((s >> 1) * 64 + n) * 8 + (s & 1);
            #pragma unroll
            for (int t4 = 0; t4 < 4; t4++)
                dst[2 * t4] = make_uint2(bf2(src[2 * t4],     src[2 * t4 + 1]),
                                         bf2(src[2 * t4 + 8], src[2 * t4 + 9]));
        }
        float* vec = g_vec + node * 256;
        if (tid < 64) {
            vec[tid]       = w3[tid * 128 + 64 + node];
            vec[64 + tid]  = b3a[node * 64 + tid];
            vec[128 + tid] = W3b[node * 64 + tid];
        }
        if (tid == 0) vec[192] = b3b[node];
    }
}

// ---------------- main kernel ----------------
__global__ void __launch_bounds__(kThreads, 1)
ctp_r9_kernel(const float* __restrict__ x, float* __restrict__ out)
{
    extern __shared__ char smem[];
    __nv_bfloat16* Xs = reinterpret_cast<__nv_bfloat16*>(smem + OFF_X);
    float* xi    = reinterpret_cast<float*>(smem + OFF_XI);
    float* w3x   = reinterpret_cast<float*>(smem + OFF_W3X);
    float* b3a_s = reinterpret_cast<float*>(smem + OFF_B3A);
    float* w3b_s = reinterpret_cast<float*>(smem + OFF_W3B);
    float* b3b_s = reinterpret_cast<float*>(smem + OFF_B3B);
    const uint4* bp1q = reinterpret_cast<const uint4*>(smem + OFF_BP);
    const uint4* bp2q = bp1q + 1024;
    const uint4* bp3q = bp1q + 1536;

    const int tid   = threadIdx.x;
    const int node  = blockIdx.y;
    const int bbase = blockIdx.x * kBT;

    // ---- staging: coalesced bulk copy of repacked weights ----
    {
        const uint4* src = reinterpret_cast<const uint4*>(g_bp + (size_t)node * kBPN);
        uint4* dst = const_cast<uint4*>(bp1q);
        #pragma unroll
        for (int t = tid; t < 2048; t += kThreads) dst[t] = src[t];
        const float* vec = g_vec + node * 256;
        if (tid < 64) {
            w3x[tid]   = vec[tid];
            b3a_s[tid] = vec[64 + tid];
            w3b_s[tid] = vec[128 + tid];
        }
        if (tid == 64) b3b_s[0] = vec[192];
    }
    // ---- X: mask col `node`, save fp32 x[:,node] ----
    {
        const float* xg = x + (size_t)bbase * 64;
        for (int idx = tid; idx < kBT * 16; idx += kThreads) {
            const int row = idx >> 4, j = idx & 15;
            float4 v = *reinterpret_cast<const float4*>(xg + row * 64 + j * 4);
            if ((node >> 2) == j) {
                float* vv = reinterpret_cast<float*>(&v);
                xi[row] = vv[node & 3];
                vv[node & 3] = 0.0f;
            }
            *reinterpret_cast<uint2*>(Xs + row * 72 + j * 4) =
                make_uint2(bf2(v.x, v.y), bf2(v.z, v.w));
        }
    }
    __syncthreads();

    // ---------------- per-warp register-chained MLP ----------------
    const int wid = tid >> 5, lane = tid & 31;
    const int tg = lane >> 2, t4 = lane & 3;
    const int r0 = wid * 32;
    const int swap = wid & 1;          // branch-order stagger

    // hoisted X A-fragments: 2 m16 tiles x 4 ksteps
    const int mat = lane >> 3, rin = lane & 7;
    const int arow = ((mat & 1) << 3) + rin;
    const int akb  = (mat >> 1) << 4;
    const uint32_t a_base = smem_u32(Xs) + (uint32_t)(r0 + arow) * 144 + akb;
    uint32_t XA[2][4][4];
    #pragma unroll
    for (int mt = 0; mt < 2; mt++)
        #pragma unroll
        for (int s = 0; s < 4; s++)
            ldmat4(XA[mt][s], a_base + mt * 16 * 144 + s * 32);

    float acc[2][8][4];
    float acc4[2][4][4];
    uint32_t A2[2][4][4];
    uint32_t A3[2][4][4];

    // ---- L1 half + L2 branch, staggered order ----
    #pragma unroll
    for (int bi = 0; bi < 2; bi++) {
        const int br = bi ^ swap;
        #pragma unroll
        for (int mt = 0; mt < 2; mt++)
            #pragma unroll
            for (int nt = 0; nt < 8; nt++)
                #pragma unroll
                for (int i = 0; i < 4; i++) acc[mt][nt][i] = 0.0f;
        #pragma unroll
        for (int sp = 0; sp < 2; sp++) {
            const uint4* bs = bp1q + sp * 512 + br * 256 + lane;
            #pragma unroll
            for (int nt = 0; nt < 8; nt++) {
                const uint4 q = bs[nt * 32];
                #pragma unroll
                for (int mt = 0; mt < 2; mt++) {
                    mma16(acc[mt][nt], XA[mt][2 * sp],     q.x, q.y);
                    mma16(acc[mt][nt], XA[mt][2 * sp + 1], q.z, q.w);
                }
            }
        }
        #pragma unroll
        for (int mt = 0; mt < 2; mt++)
            #pragma unroll
            for (int s = 0; s < 4; s++)
                pack2(A2[mt][s], acc[mt][2 * s], acc[mt][2 * s + 1]);

        #pragma unroll
        for (int mt = 0; mt < 2; mt++)
            #pragma unroll
            for (int nt = 0; nt < 4; nt++)
                #pragma unroll
                for (int i = 0; i < 4; i++) acc4[mt][nt][i] = 0.0f;
        #pragma unroll
        for (int sp = 0; sp < 2; sp++) {
            const uint4* bs = bp2q + br * 256 + sp * 128 + lane;
            #pragma unroll
            for (int nt = 0; nt < 4; nt++) {
                const uint4 q = bs[nt * 32];
                #pragma unroll
                for (int mt = 0; mt < 2; mt++) {
                    mma16(acc4[mt][nt], A2[mt][2 * sp],     q.x, q.y);
                    mma16(acc4[mt][nt], A2[mt][2 * sp + 1], q.z, q.w);
                }
            }
        }
        #pragma unroll
        for (int mt = 0; mt < 2; mt++)
            #pragma unroll
            for (int s = 0; s < 2; s++)
                pack2(A3[mt][2 * br + s], acc4[mt][2 * s], acc4[mt][2 * s + 1]);
    }

    // ---- L3 (K=64, 64 outputs) ----
    #pragma unroll
    for (int mt = 0; mt < 2; mt++)
        #pragma unroll
        for (int nt = 0; nt < 8; nt++)
            #pragma unroll
            for (int i = 0; i < 4; i++) acc[mt][nt][i] = 0.0f;
    #pragma unroll
    for (int sp = 0; sp < 2; sp++) {
        const uint4* bs = bp3q + sp * 256 + lane;
        #pragma unroll
        for (int nt = 0; nt < 8; nt++) {
            const uint4 q = bs[nt * 32];
            #pragma unroll
            for (int mt = 0; mt < 2; mt++) {
                mma16(acc[mt][nt], A3[mt][2 * sp],     q.x, q.y);
                mma16(acc[mt][nt], A3[mt][2 * sp + 1], q.z, q.w);
            }
        }
    }

    // ---- epilogue (fp32) ----
    float s2[2][2] = {{0.f, 0.f}, {0.f, 0.f}};
    #pragma unroll
    for (int mt = 0; mt < 2; mt++) {
        const int ru = r0 + 16 * mt + tg;
        const float xu = xi[ru], xl = xi[ru + 8];
        #pragma unroll
        for (int nt = 0; nt < 8; nt++) {
            const int c0 = 8 * nt + 2 * t4;
            const float wx0 = w3x[c0], wx1 = w3x[c0 + 1];
            const float ba0 = b3a_s[c0], ba1 = b3a_s[c0 + 1];
            const float wb0 = w3b_s[c0], wb1 = w3b_s[c0 + 1];
            s2[mt][0] += fmaxf(acc[mt][nt][0] + xu * wx0 + ba0, 0.f) * wb0
                       + fmaxf(acc[mt][nt][1] + xu * wx1 + ba1, 0.f) * wb1;
            s2[mt][1] += fmaxf(acc[mt][nt][2] + xl * wx0 + ba0, 0.f) * wb0
                       + fmaxf(acc[mt][nt][3] + xl * wx1 + ba1, 0.f) * wb1;
        }
    }
    const float bb = b3b_s[0];
    #pragma unroll
    for (int mt = 0; mt < 2; mt++)
        #pragma unroll
        for (int half = 0; half < 2; half++) {
            float v = s2[mt][half];
            v += __shfl_xor_sync(0xffffffff, v, 1);
            v += __shfl_xor_sync(0xffffffff, v, 2);
            if (t4 == 0) {
                const int ru = r0 + 16 * mt + tg + 8 * half;
                out[(size_t)(bbase + ru) * 64 + node] = fmaxf(v + bb, 0.f);
            }
        }
}

extern "C" void kernel_launch(void* const* d_in, const int* in_sizes, int n_in,
                              void* d_out, int out_size)
{
    (void)in_sizes; (void)n_in; (void)out_size;
    const float* x   = (const float*)d_in[0];
    const float* W1a = (const float*)d_in[1];
    const float* W1b = (const float*)d_in[2];
    const float* W2a = (const float*)d_in[3];
    const float* W2b = (const float*)d_in[4];
    const float* W3a = (const float*)d_in[5];
    const float* b3a = (const float*)d_in[6];
    const float* W3b = (const float*)d_in[7];
    const float* b3b = (const float*)d_in[8];
    float* out = (float*)d_out;

    ctp_repack_kernel<<<64, 256>>>(W1a, W1b, W2a, W2b, W3a, b3a, W3b, b3b);

    cudaFuncSetAttribute(ctp_r9_kernel,
                         cudaFuncAttributeMaxDynamicSharedMemorySize,
                         (int)SMEM_BYTES);
    dim3 grid(kB / kBT, 64);   // 32 batch tiles x 64 nodes
    ctp_r9_kernel<<<grid, kThreads, SMEM_BYTES>>>(x, out);
}

// round 10
// speedup vs baseline: 1.3514x; 1.3514x over previous
#include <cuda_runtime.h>
#include <cuda_bf16.h>
#include <cstdint>

// CausalTrajectoryPrediction: fused 3-GEMM MLP, mma.sync m16n8k16 bf16,
// register-chained, weights pre-repacked per node (repack kernel). R10 = R8
// compute structure (static branch unroll, kBT=256, 2 CTA/SM) with the only
// change being uint4-paired B fragments: one LDS.128 carries two ksteps,
// halving B-load instruction count and address ALU. (R9's dynamic branch
// indexing caused local-memory spills — reverted.)

namespace {
constexpr int kB       = 16384;
constexpr int kBT      = 256;
constexpr int kThreads = 256;

// per-node repacked weights, uint2 units; pair layout:
// frag(s,n,t4) at uint2 idx ((s>>1)*NS + n)*8 + 2*t4 + (s&1)
// -> lane reads uint4 (ksteps 2sp, 2sp+1) at uint4 idx (sp*NS + n0)*4... etc.
constexpr int kBPN = 4096;   // BP1 [0,2048) | BP2 [2048,3072) | BP3 [3072,4096)

constexpr uint32_t OFF_X   = 0;          // bf16 [256][72] = 36864
constexpr uint32_t OFF_BP  = 36864;      // 32 KB
constexpr uint32_t OFF_XI  = 69632;      // float [256]
constexpr uint32_t OFF_W3X = 70656;      // float [64]
constexpr uint32_t OFF_B3A = 70912;      // float [64]
constexpr uint32_t OFF_W3B = 71168;      // float [64]
constexpr uint32_t OFF_B3B = 71424;      // float
constexpr uint32_t SMEM_BYTES = 71440;
} // namespace

__device__ uint2 g_bp[64 * kBPN];
__device__ float g_vec[64 * 256];

__device__ __forceinline__ uint32_t smem_u32(const void* p) {
    uint32_t a;
    asm("{ .reg .u64 t; cvta.to.shared.u64 t, %1; cvt.u32.u64 %0, t; }"
        : "=r"(a) : "l"(p));
    return a;
}
__device__ __forceinline__ uint32_t bf2(float a, float b) {
    __nv_bfloat162 h = __floats2bfloat162_rn(a, b);
    return *reinterpret_cast<uint32_t*>(&h);
}
__device__ __forceinline__ void ldmat4(uint32_t r[4], uint32_t saddr) {
    asm volatile("ldmatrix.sync.aligned.m8n8.x4.shared.b16 {%0,%1,%2,%3}, [%4];"
                 : "=r"(r[0]), "=r"(r[1]), "=r"(r[2]), "=r"(r[3]) : "r"(saddr));
}
__device__ __forceinline__ void mma16(float d[4], const uint32_t a[4],
                                      uint32_t b0, uint32_t b1) {
    asm volatile(
        "mma.sync.aligned.m16n8k16.row.col.f32.bf16.bf16.f32 "
        "{%0,%1,%2,%3}, {%4,%5,%6,%7}, {%8,%9}, {%0,%1,%2,%3};"
        : "+f"(d[0]), "+f"(d[1]), "+f"(d[2]), "+f"(d[3])
        : "r"(a[0]), "r"(a[1]), "r"(a[2]), "r"(a[3]), "r"(b0), "r"(b1));
}
__device__ __forceinline__ void pack2(uint32_t a[4], const float c0[4],
                                      const float c1[4]) {
    a[0] = bf2(fmaxf(c0[0], 0.f), fmaxf(c0[1], 0.f));
    a[1] = bf2(fmaxf(c0[2], 0.f), fmaxf(c0[3], 0.f));
    a[2] = bf2(fmaxf(c1[0], 0.f), fmaxf(c1[1], 0.f));
    a[3] = bf2(fmaxf(c1[2], 0.f), fmaxf(c1[3], 0.f));
}

// ---------------- repack kernel: one block per node ----------------
__global__ void __launch_bounds__(256)
ctp_repack_kernel(const float* __restrict__ W1a, const float* __restrict__ W1b,
                  const float* __restrict__ W2a, const float* __restrict__ W2b,
                  const float* __restrict__ W3a, const float* __restrict__ b3a,
                  const float* __restrict__ W3b, const float* __restrict__ b3b)
{
    const int node = blockIdx.x;
    const int tid  = threadIdx.x;
    uint2* bp1 = g_bp + (size_t)node * kBPN;
    uint2* bp2 = bp1 + 2048;
    uint2* bp3 = bp1 + 3072;

    {   // BP1: [W1a;W2a], NS=128
        const float* w1 = W1a + (size_t)node * 4096;
        const float* w2 = W2a + (size_t)node * 4096;
        for (int t = tid; t < 512; t += 256) {
            const int n = t >> 2, s = t & 3;
            const float* src = (n < 64) ? (w1 + n * 64 + s * 16)
                                        : (w2 + (n - 64) * 64 + s * 16);
            uint2* dst = bp1 + (size_t)((s >> 1) * 128 + n) * 8 + (s & 1);
            #pragma unroll
            for (int t4 = 0; t4 < 4; t4++)
                dst[2 * t4] = make_uint2(bf2(src[2 * t4],     src[2 * t4 + 1]),
                                         bf2(src[2 * t4 + 8], src[2 * t4 + 9]));
        }
    }
    {   // BP2: br0 = W1b, br1 = W2b; NS=32 within each br half
        for (int t = tid; t < 256; t += 256) {
            const int br = t >> 7, rem = t & 127, m = rem >> 2, s = rem & 3;
            const float* src = (br ? W2b : W1b) + (size_t)node * 2048 + m * 64 + s * 16;
            uint2* dst = bp2 + (size_t)br * 512
                             + (size_t)((s >> 1) * 32 + m) * 8 + (s & 1);
            #pragma unroll
            for (int t4 = 0; t4 < 4; t4++)
                dst[2 * t4] = make_uint2(bf2(src[2 * t4],     src[2 * t4 + 1]),
                                         bf2(src[2 * t4 + 8], src[2 * t4 + 9]));
        }
    }
    {   // BP3: W3a[:,0:64], NS=64
        const float* w3 = W3a + (size_t)node * 8192;
        for (int t = tid; t < 256; t += 256) {
            const int n = t >> 2, s = t & 3;
            const float* src = w3 + n * 128 + s * 16;
            uint2* dst = bp3 + (size_t)((s >> 1) * 64 + n) * 8 + (s & 1);
            #pragma unroll
            for (int t4 = 0; t4 < 4; t4++)
                dst[2 * t4] = make_uint2(bf2(src[2 * t4],     src[2 * t4 + 1]),
                                         bf2(src[2 * t4 + 8], src[2 * t4 + 9]));
        }
        float* vec = g_vec + node * 256;
        if (tid < 64) {
            vec[tid]       = w3[tid * 128 + 64 + node];
            vec[64 + tid]  = b3a[node * 64 + tid];
            vec[128 + tid] = W3b[node * 64 + tid];
        }
        if (tid == 0) vec[192] = b3b[node];
    }
}

// ---------------- main kernel ----------------
__global__ void __launch_bounds__(kThreads, 2)
ctp_r10_kernel(const float* __restrict__ x, float* __restrict__ out)
{
    extern __shared__ char smem[];
    __nv_bfloat16* Xs = reinterpret_cast<__nv_bfloat16*>(smem + OFF_X);
    float* xi    = reinterpret_cast<float*>(smem + OFF_XI);
    float* w3x   = reinterpret_cast<float*>(smem + OFF_W3X);
    float* b3a_s = reinterpret_cast<float*>(smem + OFF_B3A);
    float* w3b_s = reinterpret_cast<float*>(smem + OFF_W3B);
    float* b3b_s = reinterpret_cast<float*>(smem + OFF_B3B);
    const uint4* bp1q = reinterpret_cast<const uint4*>(smem + OFF_BP);
    const uint4* bp2q = bp1q + 1024;
    const uint4* bp3q = bp1q + 1536;

    const int tid   = threadIdx.x;
    const int node  = blockIdx.y;
    const int bbase = blockIdx.x * kBT;

    // ---- staging: coalesced bulk copy of repacked weights ----
    {
        const uint4* src = reinterpret_cast<const uint4*>(g_bp + (size_t)node * kBPN);
        uint4* dst = reinterpret_cast<uint4*>(smem + OFF_BP);
        #pragma unroll
        for (int t = tid; t < 2048; t += kThreads) dst[t] = src[t];
        const float* vec = g_vec + node * 256;
        if (tid < 64) {
            w3x[tid]   = vec[tid];
            b3a_s[tid] = vec[64 + tid];
            w3b_s[tid] = vec[128 + tid];
        }
        if (tid == 64) b3b_s[0] = vec[192];
    }
    // ---- X: mask col `node`, save fp32 x[:,node] ----
    {
        const float* xg = x + (size_t)bbase * 64;
        for (int idx = tid; idx < kBT * 16; idx += kThreads) {
            const int row = idx >> 4, j = idx & 15;
            float4 v = *reinterpret_cast<const float4*>(xg + row * 64 + j * 4);
            if ((node >> 2) == j) {
                float* vv = reinterpret_cast<float*>(&v);
                xi[row] = vv[node & 3];
                vv[node & 3] = 0.0f;
            }
            *reinterpret_cast<uint2*>(Xs + row * 72 + j * 4) =
                make_uint2(bf2(v.x, v.y), bf2(v.z, v.w));
        }
    }
    __syncthreads();

    // ---------------- per-warp register-chained MLP (R8 path) ----------------
    const int wid = tid >> 5, lane = tid & 31;
    const int tg = lane >> 2, t4 = lane & 3;
    const int r0 = wid * 32;

    const int mat = lane >> 3, rin = lane & 7;
    const int arow = ((mat & 1) << 3) + rin;
    const int akb  = (mat >> 1) << 4;
    const uint32_t a_base0 = smem_u32(Xs) + (uint32_t)(r0 + arow) * 144 + akb;

    float acc[2][8][4];
    float acc4[2][4][4];
    uint32_t A2[2][4][4];
    uint32_t A3[2][4][4];

    // L1 half + L2 branch, br = 0 then 1 (static unroll; all indices const)
    #pragma unroll
    for (int br = 0; br < 2; br++) {
        #pragma unroll
        for (int mt = 0; mt < 2; mt++)
            #pragma unroll
            for (int nt = 0; nt < 8; nt++)
                #pragma unroll
                for (int i = 0; i < 4; i++) acc[mt][nt][i] = 0.0f;
        #pragma unroll
        for (int sp = 0; sp < 2; sp++) {
            uint32_t a0[4], a1[4];
            ldmat4(a0, a_base0 + sp * 64);                 // ksteps 2sp, 2sp+1 live
            ldmat4(a1, a_base0 + sp * 64 + 16 * 144);
            uint32_t a0b[4], a1b[4];
            ldmat4(a0b, a_base0 + sp * 64 + 32);
            ldmat4(a1b, a_base0 + sp * 64 + 32 + 16 * 144);
            const uint4* bs = bp1q + sp * 512 + br * 256 + lane;
            #pragma unroll
            for (int nt = 0; nt < 8; nt++) {
                const uint4 q = bs[nt * 32];
                mma16(acc[0][nt], a0,  q.x, q.y);
                mma16(acc[1][nt], a1,  q.x, q.y);
                mma16(acc[0][nt], a0b, q.z, q.w);
                mma16(acc[1][nt], a1b, q.z, q.w);
            }
        }
        #pragma unroll
        for (int mt = 0; mt < 2; mt++)
            #pragma unroll
            for (int s = 0; s < 4; s++)
                pack2(A2[mt][s], acc[mt][2 * s], acc[mt][2 * s + 1]);

        #pragma unroll
        for (int mt = 0; mt < 2; mt++)
            #pragma unroll
            for (int nt = 0; nt < 4; nt++)
                #pragma unroll
                for (int i = 0; i < 4; i++) acc4[mt][nt][i] = 0.0f;
        #pragma unroll
        for (int sp = 0; sp < 2; sp++) {
            const uint4* bs = bp2q + br * 256 + sp * 128 + lane;
            #pragma unroll
            for (int nt = 0; nt < 4; nt++) {
                const uint4 q = bs[nt * 32];
                mma16(acc4[0][nt], A2[0][2 * sp],     q.x, q.y);
                mma16(acc4[1][nt], A2[1][2 * sp],     q.x, q.y);
                mma16(acc4[0][nt], A2[0][2 * sp + 1], q.z, q.w);
                mma16(acc4[1][nt], A2[1][2 * sp + 1], q.z, q.w);
            }
        }
        #pragma unroll
        for (int mt = 0; mt < 2; mt++)
            #pragma unroll
            for (int s = 0; s < 2; s++)
                pack2(A3[mt][2 * br + s], acc4[mt][2 * s], acc4[mt][2 * s + 1]);
    }

    // L3 (K=64, 64 outputs)
    #pragma unroll
    for (int mt = 0; mt < 2; mt++)
        #pragma unroll
        for (int nt = 0; nt < 8; nt++)
            #pragma unroll
            for (int i = 0; i < 4; i++) acc[mt][nt][i] = 0.0f;
    #pragma unroll
    for (int sp = 0; sp < 2; sp++) {
        const uint4* bs = bp3q + sp * 256 + lane;
        #pragma unroll
        for (int nt = 0; nt < 8; nt++) {
            const uint4 q = bs[nt * 32];
            mma16(acc[0][nt], A3[0][2 * sp],     q.x, q.y);
            mma16(acc[1][nt], A3[1][2 * sp],     q.x, q.y);
            mma16(acc[0][nt], A3[0][2 * sp + 1], q.z, q.w);
            mma16(acc[1][nt], A3[1][2 * sp + 1], q.z, q.w);
        }
    }

    // epilogue (fp32)
    float s2[2][2] = {{0.f, 0.f}, {0.f, 0.f}};
    #pragma unroll
    for (int mt = 0; mt < 2; mt++) {
        const int ru = r0 + 16 * mt + tg;
        const float xu = xi[ru], xl = xi[ru + 8];
        #pragma unroll
        for (int nt = 0; nt < 8; nt++) {
            const int c0 = 8 * nt + 2 * t4;
            const float wx0 = w3x[c0], wx1 = w3x[c0 + 1];
            const float ba0 = b3a_s[c0], ba1 = b3a_s[c0 + 1];
            const float wb0 = w3b_s[c0], wb1 = w3b_s[c0 + 1];
            s2[mt][0] += fmaxf(acc[mt][nt][0] + xu * wx0 + ba0, 0.f) * wb0
                       + fmaxf(acc[mt][nt][1] + xu * wx1 + ba1, 0.f) * wb1;
            s2[mt][1] += fmaxf(acc[mt][nt][2] + xl * wx0 + ba0, 0.f) * wb0
                       + fmaxf(acc[mt][nt][3] + xl * wx1 + ba1, 0.f) * wb1;
        }
    }
    const float bb = b3b_s[0];
    #pragma unroll
    for (int mt = 0; mt < 2; mt++)
        #pragma unroll
        for (int half = 0; half < 2; half++) {
            float v = s2[mt][half];
            v += __shfl_xor_sync(0xffffffff, v, 1);
            v += __shfl_xor_sync(0xffffffff, v, 2);
            if (t4 == 0) {
                const int ru = r0 + 16 * mt + tg + 8 * half;
                out[(size_t)(bbase + ru) * 64 + node] = fmaxf(v + bb, 0.f);
            }
        }
}

extern "C" void kernel_launch(void* const* d_in, const int* in_sizes, int n_in,
                              void* d_out, int out_size)
{
    (void)in_sizes; (void)n_in; (void)out_size;
    const float* x   = (const float*)d_in[0];
    const float* W1a = (const float*)d_in[1];
    const float* W1b = (const float*)d_in[2];
    const float* W2a = (const float*)d_in[3];
    const float* W2b = (const float*)d_in[4];
    const float* W3a = (const float*)d_in[5];
    const float* b3a = (const float*)d_in[6];
    const float* W3b = (const float*)d_in[7];
    const float* b3b = (const float*)d_in[8];
    float* out = (float*)d_out;

    ctp_repack_kernel<<<64, 256>>>(W1a, W1b, W2a, W2b, W3a, b3a, W3b, b3b);

    cudaFuncSetAttribute(ctp_r10_kernel,
                         cudaFuncAttributeMaxDynamicSharedMemorySize,
                         (int)SMEM_BYTES);
    dim3 grid(kB / kBT, 64);   // 64 batch tiles x 64 nodes
    ctp_r10_kernel<<<grid, kThreads, SMEM_BYTES>>>(x, out);
}

// round 11
// speedup vs baseline: 1.3540x; 1.0019x over previous
#include <cuda_runtime.h>
#include <cuda_bf16.h>
#include <cstdint>

// CausalTrajectoryPrediction: fused 3-GEMM MLP, mma.sync m16n8k16 bf16,
// register-chained, weights pre-repacked per node. R11 = R8 compute path
// (best: 130.5us) + cp.async weight staging (overlapped with X staging),
// packed per-lane epilogue tables (2 LDS/nt instead of 6 scalar broadcasts),
// and relu folded into bf16 pack via __hmax2 (bit-identical).

namespace {
constexpr int kB       = 16384;
constexpr int kBT      = 256;
constexpr int kThreads = 256;

constexpr int kBPN = 4096;   // uint2/node: BP1 [0,2048) BP2 [2048,3072) BP3 [3072,4096)

constexpr uint32_t OFF_X   = 0;          // bf16 [256][72] = 36864
constexpr uint32_t OFF_BP  = 36864;      // 32 KB
constexpr uint32_t OFF_XI  = 69632;      // float [256]
constexpr uint32_t OFF_VEC = 70656;      // float[256]: epa[128] epw[64] b3b spare
constexpr uint32_t SMEM_BYTES = 71680;
} // namespace

__device__ uint2 g_bp[64 * kBPN];        // repacked weight fragments
__device__ float g_vec[64 * 256];        // packed epilogue tables per node

__device__ __forceinline__ uint32_t smem_u32(const void* p) {
    uint32_t a;
    asm("{ .reg .u64 t; cvta.to.shared.u64 t, %1; cvt.u32.u64 %0, t; }"
        : "=r"(a) : "l"(p));
    return a;
}
__device__ __forceinline__ uint32_t bf2(float a, float b) {
    __nv_bfloat162 h = __floats2bfloat162_rn(a, b);
    return *reinterpret_cast<uint32_t*>(&h);
}
// pack + relu (relu applied on bf16 pair; identical to fmax-then-round)
__device__ __forceinline__ uint32_t bf2r(float a, float b) {
    __nv_bfloat162 h = __floats2bfloat162_rn(a, b);
    h = __hmax2(h, __nv_bfloat162(__float2bfloat16(0.f), __float2bfloat16(0.f)));
    return *reinterpret_cast<uint32_t*>(&h);
}
__device__ __forceinline__ void ldmat4(uint32_t r[4], uint32_t saddr) {
    asm volatile("ldmatrix.sync.aligned.m8n8.x4.shared.b16 {%0,%1,%2,%3}, [%4];"
                 : "=r"(r[0]), "=r"(r[1]), "=r"(r[2]), "=r"(r[3]) : "r"(saddr));
}
__device__ __forceinline__ void mma16(float d[4], const uint32_t a[4], uint2 b) {
    asm volatile(
        "mma.sync.aligned.m16n8k16.row.col.f32.bf16.bf16.f32 "
        "{%0,%1,%2,%3}, {%4,%5,%6,%7}, {%8,%9}, {%0,%1,%2,%3};"
        : "+f"(d[0]), "+f"(d[1]), "+f"(d[2]), "+f"(d[3])
        : "r"(a[0]), "r"(a[1]), "r"(a[2]), "r"(a[3]), "r"(b.x), "r"(b.y));
}
__device__ __forceinline__ void pack2(uint32_t a[4], const float c0[4],
                                      const float c1[4]) {
    a[0] = bf2r(c0[0], c0[1]);
    a[1] = bf2r(c0[2], c0[3]);
    a[2] = bf2r(c1[0], c1[1]);
    a[3] = bf2r(c1[2], c1[3]);
}
__device__ __forceinline__ void cp_async16(uint32_t saddr, const void* gaddr) {
    asm volatile("cp.async.cg.shared.global [%0], [%1], 16;"
                 :: "r"(saddr), "l"(gaddr) : "memory");
}

// ---------------- repack kernel: one block per node ----------------
__global__ void __launch_bounds__(256)
ctp_repack_kernel(const float* __restrict__ W1a, const float* __restrict__ W1b,
                  const float* __restrict__ W2a, const float* __restrict__ W2b,
                  const float* __restrict__ W3a, const float* __restrict__ b3a,
                  const float* __restrict__ W3b, const float* __restrict__ b3b)
{
    const int node = blockIdx.x;
    const int tid  = threadIdx.x;
    uint2* bp1 = g_bp + (size_t)node * kBPN;
    uint2* bp2 = bp1 + 2048;
    uint2* bp3 = bp1 + 3072;

    {   // BP1: [W1a;W2a] as B[n=h 0..127][k], frag layout (R8)
        const float* w1 = W1a + (size_t)node * 4096;
        const float* w2 = W2a + (size_t)node * 4096;
        for (int t = tid; t < 512; t += 256) {
            const int n = t >> 2, s = t & 3;
            const float* src = (n < 64) ? (w1 + n * 64 + s * 16)
                                        : (w2 + (n - 64) * 64 + s * 16);
            uint2* dst = bp1 + (size_t)(s * 128 + n) * 4;
            #pragma unroll
            for (int t4 = 0; t4 < 4; t4++)
                dst[t4] = make_uint2(bf2(src[2 * t4],     src[2 * t4 + 1]),
                                     bf2(src[2 * t4 + 8], src[2 * t4 + 9]));
        }
    }
    {   // BP2: br0 = W1b, br1 = W2b
        for (int t = tid; t < 256; t += 256) {
            const int br = t >> 7, rem = t & 127, m = rem >> 2, s = rem & 3;
            const float* src = (br ? W2b : W1b) + (size_t)node * 2048 + m * 64 + s * 16;
            uint2* dst = bp2 + (size_t)((br * 4 + s) * 32 + m) * 4;
            #pragma unroll
            for (int t4 = 0; t4 < 4; t4++)
                dst[t4] = make_uint2(bf2(src[2 * t4],     src[2 * t4 + 1]),
                                     bf2(src[2 * t4 + 8], src[2 * t4 + 9]));
        }
    }
    {   // BP3: W3a[:,0:64] as B[n=h][k=c]
        const float* w3 = W3a + (size_t)node * 8192;
        for (int t = tid; t < 256; t += 256) {
            const int n = t >> 2, s = t & 3;
            const float* src = w3 + n * 128 + s * 16;
            uint2* dst = bp3 + (size_t)(s * 64 + n) * 4;
            #pragma unroll
            for (int t4 = 0; t4 < 4; t4++)
                dst[t4] = make_uint2(bf2(src[2 * t4],     src[2 * t4 + 1]),
                                     bf2(src[2 * t4 + 8], src[2 * t4 + 9]));
        }
        // packed epilogue tables: epa[nt*4+t4] = {wx0,wx1,ba0,ba1},
        //                          epw[nt*4+t4] = {wb0,wb1}
        float* vec = g_vec + node * 256;
        if (tid < 32) {
            const int nt = tid >> 2, t4 = tid & 3;
            const int c0 = 8 * nt + 2 * t4;
            float4* epa = reinterpret_cast<float4*>(vec);
            float2* epw = reinterpret_cast<float2*>(vec + 128);
            epa[tid] = make_float4(w3[c0 * 128 + 64 + node],
                                   w3[(c0 + 1) * 128 + 64 + node],
                                   b3a[node * 64 + c0],
                                   b3a[node * 64 + c0 + 1]);
            epw[tid] = make_float2(W3b[node * 64 + c0], W3b[node * 64 + c0 + 1]);
        }
        if (tid == 32) vec[192] = b3b[node];
    }
}

// ---------------- main kernel ----------------
__global__ void __launch_bounds__(kThreads, 2)
ctp_r11_kernel(const float* __restrict__ x, float* __restrict__ out)
{
    extern __shared__ char smem[];
    __nv_bfloat16* Xs = reinterpret_cast<__nv_bfloat16*>(smem + OFF_X);
    float* xi = reinterpret_cast<float*>(smem + OFF_XI);
    const float4* epa = reinterpret_cast<const float4*>(smem + OFF_VEC);
    const float2* epw = reinterpret_cast<const float2*>(smem + OFF_VEC + 512);
    const float*  vecs = reinterpret_cast<const float*>(smem + OFF_VEC);
    const uint2* bp1 = reinterpret_cast<const uint2*>(smem + OFF_BP);
    const uint2* bp2 = bp1 + 2048;
    const uint2* bp3 = bp1 + 3072;

    const int tid   = threadIdx.x;
    const int node  = blockIdx.y;
    const int bbase = blockIdx.x * kBT;

    // ---- weight + table staging via cp.async (overlaps X staging below) ----
    {
        const char* src = reinterpret_cast<const char*>(g_bp + (size_t)node * kBPN);
        const uint32_t dstb = smem_u32(smem + OFF_BP);
        #pragma unroll
        for (int i = 0; i < 8; i++) {
            const int t = tid + i * kThreads;
            cp_async16(dstb + t * 16, src + t * 16);
        }
        if (tid < 64)
            cp_async16(smem_u32(smem + OFF_VEC) + tid * 16,
                       reinterpret_cast<const char*>(g_vec + node * 256) + tid * 16);
        asm volatile("cp.async.commit_group;" ::: "memory");
    }
    // ---- X: mask col `node`, save fp32 x[:,node] ----
    {
        const float* xg = x + (size_t)bbase * 64;
        for (int idx = tid; idx < kBT * 16; idx += kThreads) {
            const int row = idx >> 4, j = idx & 15;
            float4 v = *reinterpret_cast<const float4*>(xg + row * 64 + j * 4);
            if ((node >> 2) == j) {
                float* vv = reinterpret_cast<float*>(&v);
                xi[row] = vv[node & 3];
                vv[node & 3] = 0.0f;
            }
            *reinterpret_cast<uint2*>(Xs + row * 72 + j * 4) =
                make_uint2(bf2(v.x, v.y), bf2(v.z, v.w));
        }
    }
    asm volatile("cp.async.wait_group 0;" ::: "memory");
    __syncthreads();

    // ---------------- per-warp register-chained MLP (R8 path) ----------------
    const int wid = tid >> 5, lane = tid & 31;
    const int tg = lane >> 2, t4 = lane & 3;
    const int r0 = wid * 32;

    const int mat = lane >> 3, rin = lane & 7;
    const int arow = ((mat & 1) << 3) + rin;
    const int akb  = (mat >> 1) << 4;
    const uint32_t a_base0 = smem_u32(Xs) + (uint32_t)(r0 + arow) * 144 + akb;

    float acc[2][8][4];
    float acc4[2][4][4];
    uint32_t A2[2][4][4];
    uint32_t A3[2][4][4];

    // L1 half + L2 branch, br = 0 then 1 (static unroll)
    #pragma unroll
    for (int br = 0; br < 2; br++) {
        #pragma unroll
        for (int mt = 0; mt < 2; mt++)
            #pragma unroll
            for (int nt = 0; nt < 8; nt++)
                #pragma unroll
                for (int i = 0; i < 4; i++) acc[mt][nt][i] = 0.0f;
        #pragma unroll
        for (int s = 0; s < 4; s++) {
            uint32_t a0[4], a1[4];
            ldmat4(a0, a_base0 + s * 32);
            ldmat4(a1, a_base0 + s * 32 + 16 * 144);
            const uint2* bs = bp1 + (size_t)s * 512 + br * 256 + lane;
            #pragma unroll
            for (int nt = 0; nt < 8; nt++) {
                const uint2 bv = bs[nt * 32];
                mma16(acc[0][nt], a0, bv);
                mma16(acc[1][nt], a1, bv);
            }
        }
        #pragma unroll
        for (int mt = 0; mt < 2; mt++)
            #pragma unroll
            for (int s = 0; s < 4; s++)
                pack2(A2[mt][s], acc[mt][2 * s], acc[mt][2 * s + 1]);

        #pragma unroll
        for (int mt = 0; mt < 2; mt++)
            #pragma unroll
            for (int nt = 0; nt < 4; nt++)
                #pragma unroll
                for (int i = 0; i < 4; i++) acc4[mt][nt][i] = 0.0f;
        #pragma unroll
        for (int s = 0; s < 4; s++) {
            const uint2* bs = bp2 + (size_t)(br * 4 + s) * 128 + lane;
            #pragma unroll
            for (int nt = 0; nt < 4; nt++) {
                const uint2 bv = bs[nt * 32];
                mma16(acc4[0][nt], A2[0][s], bv);
                mma16(acc4[1][nt], A2[1][s], bv);
            }
        }
        #pragma unroll
        for (int mt = 0; mt < 2; mt++)
            #pragma unroll
            for (int s = 0; s < 2; s++)
                pack2(A3[mt][2 * br + s], acc4[mt][2 * s], acc4[mt][2 * s + 1]);
    }

    // L3 (K=64, 64 outputs)
    #pragma unroll
    for (int mt = 0; mt < 2; mt++)
        #pragma unroll
        for (int nt = 0; nt < 8; nt++)
            #pragma unroll
            for (int i = 0; i < 4; i++) acc[mt][nt][i] = 0.0f;
    #pragma unroll
    for (int s = 0; s < 4; s++) {
        const uint2* bs = bp3 + (size_t)s * 256 + lane;
        #pragma unroll
        for (int nt = 0; nt < 8; nt++) {
            const uint2 bv = bs[nt * 32];
            mma16(acc[0][nt], A3[0][s], bv);
            mma16(acc[1][nt], A3[1][s], bv);
        }
    }

    // epilogue (fp32, packed tables): h = relu(D3 + xi*wx + ba); out = relu(h.wb + bb)
    const float xu0 = xi[r0 + tg],      xl0 = xi[r0 + tg + 8];
    const float xu1 = xi[r0 + 16 + tg], xl1 = xi[r0 + 16 + tg + 8];
    float s2[2][2] = {{0.f, 0.f}, {0.f, 0.f}};
    #pragma unroll
    for (int nt = 0; nt < 8; nt++) {
        const float4 ea = epa[nt * 4 + t4];   // {wx0, wx1, ba0, ba1}
        const float2 ew = epw[nt * 4 + t4];   // {wb0, wb1}
        s2[0][0] += fmaxf(acc[0][nt][0] + xu0 * ea.x + ea.z, 0.f) * ew.x
                  + fmaxf(acc[0][nt][1] + xu0 * ea.y + ea.w, 0.f) * ew.y;
        s2[0][1] += fmaxf(acc[0][nt][2] + xl0 * ea.x + ea.z, 0.f) * ew.x
                  + fmaxf(acc[0][nt][3] + xl0 * ea.y + ea.w, 0.f) * ew.y;
        s2[1][0] += fmaxf(acc[1][nt][0] + xu1 * ea.x + ea.z, 0.f) * ew.x
                  + fmaxf(acc[1][nt][1] + xu1 * ea.y + ea.w, 0.f) * ew.y;
        s2[1][1] += fmaxf(acc[1][nt][2] + xl1 * ea.x + ea.z, 0.f) * ew.x
                  + fmaxf(acc[1][nt][3] + xl1 * ea.y + ea.w, 0.f) * ew.y;
    }
    const float bb = vecs[192];
    #pragma unroll
    for (int mt = 0; mt < 2; mt++)
        #pragma unroll
        for (int half = 0; half < 2; half++) {
            float v = s2[mt][half];
            v += __shfl_xor_sync(0xffffffff, v, 1);
            v += __shfl_xor_sync(0xffffffff, v, 2);
            if (t4 == 0) {
                const int ru = r0 + 16 * mt + tg + 8 * half;
                out[(size_t)(bbase + ru) * 64 + node] = fmaxf(v + bb, 0.f);
            }
        }
}

extern "C" void kernel_launch(void* const* d_in, const int* in_sizes, int n_in,
                              void* d_out, int out_size)
{
    (void)in_sizes; (void)n_in; (void)out_size;
    const float* x   = (const float*)d_in[0];
    const float* W1a = (const float*)d_in[1];
    const float* W1b = (const float*)d_in[2];
    const float* W2a = (const float*)d_in[3];
    const float* W2b = (const float*)d_in[4];
    const float* W3a = (const float*)d_in[5];
    const float* b3a = (const float*)d_in[6];
    const float* W3b = (const float*)d_in[7];
    const float* b3b = (const float*)d_in[8];
    float* out = (float*)d_out;

    ctp_repack_kernel<<<64, 256>>>(W1a, W1b, W2a, W2b, W3a, b3a, W3b, b3b);

    cudaFuncSetAttribute(ctp_r11_kernel,
                         cudaFuncAttributeMaxDynamicSharedMemorySize,
                         (int)SMEM_BYTES);
    dim3 grid(kB / kBT, 64);   // 64 batch tiles x 64 nodes
    ctp_r11_kernel<<<grid, kThreads, SMEM_BYTES>>>(x, out);
}